// round 15
// baseline (speedup 1.0000x reference)
#include <cuda_runtime.h>
#include <math.h>

#define BATCH  2
#define SEQLEN 2048
#define H      512
#define NST    64
#define M      4           // virtual (compressed) modes
#define MP     2           // mode pairs (f32x2)
#define TCH    16          // timesteps per chunk (= per warp)
#define NWARP  8           // warps per CTA = chunks per group
#define NGRP   16          // chunk groups per (b,hw) column
#define NCOL   (BATCH * 16) // 32 columns; column = (b, hw)

typedef unsigned long long u64;

// per-group aggregates: [col][g][j][lane]
__device__ u64 g_R[NCOL * NGRP * MP * 32];
// one flag per (col, g), padded to 128B; zeroed by a memset node each launch
__device__ int g_flag[NCOL * NGRP * 32];

// Chebyshev nodes (M=4) over [rsqrt(2), rsqrt(65/64)]
__constant__ float f_node[M] = {
    0.981437f, 0.904371f, 0.795253f, 0.718187f
};

__device__ __forceinline__ u64 pack2(float lo, float hi) {
    u64 r; asm("mov.b64 %0, {%1, %2};" : "=l"(r) : "f"(lo), "f"(hi)); return r;
}
__device__ __forceinline__ void unpack2(u64 v, float& lo, float& hi) {
    asm("mov.b64 {%0, %1}, %2;" : "=f"(lo), "=f"(hi) : "l"(v));
}
__device__ __forceinline__ u64 fma2_(u64 a, u64 b, u64 c) {
    u64 d; asm("fma.rn.f32x2 %0, %1, %2, %3;" : "=l"(d) : "l"(a), "l"(b), "l"(c)); return d;
}
__device__ __forceinline__ u64 mul2_(u64 a, u64 b) {
    u64 d; asm("mul.rn.f32x2 %0, %1, %2;" : "=l"(d) : "l"(a), "l"(b)); return d;
}
__device__ __forceinline__ u64 add2_(u64 a, u64 b) {
    u64 d; asm("add.rn.f32x2 %0, %1, %2;" : "=l"(d) : "l"(a), "l"(b)); return d;
}
__device__ __forceinline__ int ld_acq(const int* p) {
    int v; asm volatile("ld.acquire.gpu.s32 %0, [%1];" : "=r"(v) : "l"(p) : "memory"); return v;
}
__device__ __forceinline__ void st_rel(int* p, int v) {
    asm volatile("st.release.gpu.s32 [%0], %1;" :: "l"(p), "r"(v) : "memory");
}

// out = base^e, e in [0,7], MP=2 pairs
__device__ __forceinline__ void pow_e7(const u64* base, int e, u64* out) {
    u64 p0 = pack2(1.0f, 1.0f), p1 = p0;
    u64 b0 = base[0], b1 = base[1];
    if (e & 1) { p0 = mul2_(p0, b0); p1 = mul2_(p1, b1); }
    b0 = mul2_(b0, b0); b1 = mul2_(b1, b1);
    if (e & 2) { p0 = mul2_(p0, b0); p1 = mul2_(p1, b1); }
    b0 = mul2_(b0, b0); b1 = mul2_(b1, b1);
    if (e & 4) { p0 = mul2_(p0, b0); p1 = mul2_(p1, b1); }
    out[0] = p0; out[1] = p1;
}

// out = base^e, e in [0,15], MP=2 pairs
__device__ __forceinline__ void pow_e15(const u64* base, int e, u64* out) {
    u64 p0 = pack2(1.0f, 1.0f), p1 = p0;
    u64 b0 = base[0], b1 = base[1];
    if (e & 1) { p0 = mul2_(p0, b0); p1 = mul2_(p1, b1); }
    b0 = mul2_(b0, b0); b1 = mul2_(b1, b1);
    if (e & 2) { p0 = mul2_(p0, b0); p1 = mul2_(p1, b1); }
    b0 = mul2_(b0, b0); b1 = mul2_(b1, b1);
    if (e & 4) { p0 = mul2_(p0, b0); p1 = mul2_(p1, b1); }
    b0 = mul2_(b0, b0); b1 = mul2_(b1, b1);
    if (e & 8) { p0 = mul2_(p0, b0); p1 = mul2_(p1, b1); }
    out[0] = p0; out[1] = p1;
}

// ------------------------------------------------------------------ fused
// Single kernel, grid 512 = (col, g), block 256, chunk = g*8+w, TCH=16.
// occ 4 -> all 512 CTAs resident (single wave). Coefficients per CTA in smem
// under the u-load burst. Receive done ONCE per CTA (warp 0) and broadcast
// via smem (second __syncthreads) — removes the 8x redundant carry Horner.
__global__ __launch_bounds__(256, 4)
void s4_fused(const float* __restrict__ u,
              const float* __restrict__ Dp,
              float* __restrict__ y,
              const float* __restrict__ B_re,
              const float* __restrict__ C_re,
              const float* __restrict__ log_dt)
{
    __shared__ u64   sE [NWARP][MP][32];
    __shared__ u64   sEq[NWARP][MP][32];
    __shared__ u64   sS[MP][32];          // received carry (broadcast)
    __shared__ float sL[NST][M];          // Lagrange basis at true modes
    __shared__ float sAn[NST];            // A_n values
    __shared__ float sDelta[32];          // delta per local h
    __shared__ float sPart[8][32][M];     // c~ partial sums per octet
    __shared__ float sA[32][M], sC[32][M], sQ[32][M], sQI[32][M];

    const int tid  = threadIdx.x;
    const int col  = blockIdx.x & (NCOL - 1);   // (b, hw)
    const int g    = blockIdx.x >> 5;           // group 0..15; low g = low bid
    const int w    = tid >> 5;
    const int lane = tid & 31;
    const int b    = col >> 4;
    const int hw   = col & 15;
    const int h    = hw * 32 + lane;

    const int chunk = g * NWARP + w;
    const size_t base = ((size_t)b * SEQLEN + (size_t)chunk * TCH) * H + h;
    const float* ub = u + base;

    // ---- phase A: issue ALL u loads first ----
    float uu[TCH];
#pragma unroll
    for (int t = 0; t < TCH; ++t) uu[t] = ub[(size_t)t * H];

    // ---- phase B: coefficients, hidden under the load burst ----
    if (tid < NST) {
        const float An = rsqrtf(1.0f + (float)(tid + 1) * (1.0f / 64.0f));
        sAn[tid] = An;
#pragma unroll
        for (int m = 0; m < M; ++m) {
            float num = 1.0f, den = 1.0f;
#pragma unroll
            for (int i = 0; i < M; ++i) {
                if (i == m) continue;
                num *= (An - f_node[i]);
                den *= (f_node[m] - f_node[i]);
            }
            sL[tid][m] = num / den;
        }
    }
    if (tid < 32) sDelta[tid] = expf(log_dt[hw * 32 + tid]);
    __syncthreads();

    {
        const int k  = tid >> 5;   // 0..7: true-mode octet
        const int hl = tid & 31;
        const float delta = sDelta[hl];
        float cm[M] = {0.0f, 0.0f, 0.0f, 0.0f};
#pragma unroll
        for (int i = 0; i < 8; ++i) {
            const int n = k * 8 + i;
            const float x = delta * sAn[n];                       // <= 1e-3
            const float em = x * fmaf(x, fmaf(x, (1.0f / 6.0f), 0.5f), 1.0f); // expm1
            const float cn = em * B_re[n] * delta * C_re[n];
#pragma unroll
            for (int m = 0; m < M; ++m)
                cm[m] = fmaf(cn, sL[n][m], cm[m]);
        }
#pragma unroll
        for (int m = 0; m < M; ++m) sPart[k][hl][m] = cm[m];

        if (k < M) {   // (hl, m=k): a, q=a^16, qi=1/a^128
            const float x = delta * f_node[k];                    // <= 1e-3
            const float am = 1.0f + x * fmaf(x, fmaf(x, (1.0f / 6.0f), 0.5f), 1.0f);
            float qm = am;
#pragma unroll
            for (int s = 0; s < 4; ++s) qm *= qm;                 // a^16
            float q128 = qm;
#pragma unroll
            for (int s = 0; s < 3; ++s) q128 *= q128;             // a^128
            sA[hl][k]  = am;
            sQ[hl][k]  = qm;
            sQI[hl][k] = 1.0f / q128;
        }
    }
    __syncthreads();
    if (tid < 32 * M) {   // reduce c~ over the 8 octets
        const int hl = tid & 31, m = tid >> 5;
        float s = 0.0f;
#pragma unroll
        for (int k = 0; k < 8; ++k) s += sPart[k][hl][m];
        sC[hl][m] = s;
    }
    __syncthreads();

    u64 a[MP], q[MP];
#pragma unroll
    for (int j = 0; j < MP; ++j) {
        a[j] = pack2(sA[lane][2 * j], sA[lane][2 * j + 1]);
        q[j] = pack2(sQ[lane][2 * j], sQ[lane][2 * j + 1]);
    }

    // ---- local zero-seed scan -> E ----
    u64 z[MP] = {0ull, 0ull};
#pragma unroll
    for (int t = 0; t < TCH; ++t) {
        const u64 ubb = pack2(uu[t], uu[t]);
        z[0] = fma2_(a[0], z[0], ubb);
        z[1] = fma2_(a[1], z[1], ubb);
    }

    // stage E and q^{7-w} * E (pre-scaled for the publish add-tree)
    {
        u64 qw7[MP];
        pow_e7(q, (NWARP - 1) - w, qw7);
#pragma unroll
        for (int j = 0; j < MP; ++j) {
            sE [w][j][lane] = z[j];
            sEq[w][j][lane] = mul2_(qw7[j], z[j]);
        }
    }
    __syncthreads();   // sync1: E ready

    // warp 7: publish R_g = sum_i q^{7-i} E_i via add-tree (cross-CTA path)
    if (w == NWARP - 1 && g < NGRP - 1) {
        u64* op = g_R + ((size_t)(col * NGRP + g) * MP) * 32 + lane;
#pragma unroll
        for (int j = 0; j < MP; ++j) {
            const u64 s01 = add2_(sEq[0][j][lane], sEq[1][j][lane]);
            const u64 s23 = add2_(sEq[2][j][lane], sEq[3][j][lane]);
            const u64 s45 = add2_(sEq[4][j][lane], sEq[5][j][lane]);
            const u64 s67 = add2_(sEq[6][j][lane], sEq[7][j][lane]);
            op[(size_t)j * 32] = add2_(add2_(s01, s23), add2_(s45, s67));
        }
        __syncwarp();
        if (lane == 0) st_rel(&g_flag[(col * NGRP + g) * 32], 1);
    }

    // warp 0: receive ONCE; S = sum_{g2<g} qG^{g-1-g2} R_{g2},  qG = q^8
    if (w == 0) {
        u64 S0[MP] = {0ull, 0ull};
        if (g > 0) {
            if (lane < g) {
                const int* fp = &g_flag[(col * NGRP + lane) * 32];
                while (ld_acq(fp) == 0) { __nanosleep(20); }
            }
            __syncwarp();

            u64 qG[MP];
#pragma unroll
            for (int j = 0; j < MP; ++j) {
                const u64 q2v = mul2_(q[j], q[j]);
                const u64 q4v = mul2_(q2v, q2v);
                qG[j] = mul2_(q4v, q4v);
            }
            // T = sum_{g2=0}^{14} qG^{14-g2} V_{g2} = qG^{15-g} * S (V=R if g2<g)
            u64 T[MP] = {0ull, 0ull};
#pragma unroll
            for (int g2 = 0; g2 < NGRP - 1; ++g2) {
                u64 v0 = 0ull, v1 = 0ull;
                if (g2 < g) {
                    const u64* rp = g_R + ((size_t)(col * NGRP + g2) * MP) * 32 + lane;
                    v0 = rp[0 * 32];
                    v1 = rp[1 * 32];
                }
                T[0] = fma2_(qG[0], T[0], v0);
                T[1] = fma2_(qG[1], T[1], v1);
            }
            // S = T * qGi^{15-g}
            u64 qGi[MP];
#pragma unroll
            for (int j = 0; j < MP; ++j)
                qGi[j] = pack2(sQI[lane][2 * j], sQI[lane][2 * j + 1]);
            u64 pw[MP];
            pow_e15(qGi, (NGRP - 1) - g, pw);
#pragma unroll
            for (int j = 0; j < MP; ++j) S0[j] = mul2_(T[j], pw[j]);
        }
#pragma unroll
        for (int j = 0; j < MP; ++j) sS[j][lane] = S0[j];
    }

    // all warps: P_w = sum_{i<w} q^{w-1-i} E_i  (overlaps warp-0 receive)
    u64 P[MP] = {0ull, 0ull};
    for (int i = 0; i < w; ++i) {
#pragma unroll
        for (int j = 0; j < MP; ++j)
            P[j] = fma2_(q[j], P[j], sE[i][j][lane]);
    }
    u64 qp[MP];
    pow_e7(q, w, qp);

    __syncthreads();   // sync2: S ready

    // seed = q^w * S + P_w, then output scan (writes y exactly once)
    u64 zz[MP];
#pragma unroll
    for (int j = 0; j < MP; ++j) zz[j] = fma2_(qp[j], sS[j][lane], P[j]);

    u64 c[MP];
#pragma unroll
    for (int j = 0; j < MP; ++j)
        c[j] = pack2(sC[lane][2 * j], sC[lane][2 * j + 1]);
    const float Dh = Dp[h];

    float* yb = y + base;
#pragma unroll
    for (int t = 0; t < TCH; ++t) {
        const u64 ubb = pack2(uu[t], uu[t]);
        zz[0] = fma2_(a[0], zz[0], ubb);
        zz[1] = fma2_(a[1], zz[1], ubb);
        u64 ac0 = fma2_(c[0], zz[0], 0ull);
        ac0 = fma2_(c[1], zz[1], ac0);
        float x0, x1; unpack2(ac0, x0, x1);
        yb[(size_t)t * H] = fmaf(Dh, uu[t], x0 + x1);
    }
}

extern "C" void kernel_launch(void* const* d_in, const int* in_sizes, int n_in,
                              void* d_out, int out_size)
{
    const float* u      = (const float*)d_in[0];
    const float* B_re   = (const float*)d_in[1];
    const float* C_re   = (const float*)d_in[2];
    const float* log_dt = (const float*)d_in[3];
    const float* Dp     = (const float*)d_in[4];
    float* y = (float*)d_out;

    // zero the carry flags (graph-capturable async memset; no allocs)
    void* fp = nullptr;
    cudaGetSymbolAddress(&fp, g_flag);
    cudaMemsetAsync(fp, 0, sizeof(int) * NCOL * NGRP * 32);

    s4_fused<<<NCOL * NGRP, NWARP * 32>>>(u, Dp, y, B_re, C_re, log_dt);
}

// round 16
// speedup vs baseline: 1.0173x; 1.0173x over previous
#include <cuda_runtime.h>
#include <math.h>

#define BATCH  2
#define SEQLEN 2048
#define H      512
#define NST    64
#define M      4           // virtual (compressed) modes
#define MP     2           // mode pairs (f32x2)
#define TCH    16          // timesteps per chunk (= per warp)
#define NWARP  4           // warps per CTA = chunks per group
#define NGRP   32          // chunk groups per (b,hw) column
#define NCOL   (BATCH * 16) // 32 columns; column = (b, hw)

typedef unsigned long long u64;

// per-group aggregates: [col][g][j][lane]
__device__ u64 g_R[NCOL * NGRP * MP * 32];
// per-READER flag slots: [col][reader][src]; each slot has exactly one reader
// which resets it after consuming -> zero state across graph replays, no memset
__device__ int g_flag2[NCOL * NGRP * NGRP];

// Chebyshev nodes (M=4) over [rsqrt(2), rsqrt(65/64)]
__constant__ float f_node[M] = {
    0.981437f, 0.904371f, 0.795253f, 0.718187f
};

__device__ __forceinline__ u64 pack2(float lo, float hi) {
    u64 r; asm("mov.b64 %0, {%1, %2};" : "=l"(r) : "f"(lo), "f"(hi)); return r;
}
__device__ __forceinline__ void unpack2(u64 v, float& lo, float& hi) {
    asm("mov.b64 {%0, %1}, %2;" : "=f"(lo), "=f"(hi) : "l"(v));
}
__device__ __forceinline__ u64 fma2_(u64 a, u64 b, u64 c) {
    u64 d; asm("fma.rn.f32x2 %0, %1, %2, %3;" : "=l"(d) : "l"(a), "l"(b), "l"(c)); return d;
}
__device__ __forceinline__ u64 mul2_(u64 a, u64 b) {
    u64 d; asm("mul.rn.f32x2 %0, %1, %2;" : "=l"(d) : "l"(a), "l"(b)); return d;
}
__device__ __forceinline__ int ld_acq(const int* p) {
    int v; asm volatile("ld.acquire.gpu.s32 %0, [%1];" : "=r"(v) : "l"(p) : "memory"); return v;
}
__device__ __forceinline__ void st_rel(int* p, int v) {
    asm volatile("st.release.gpu.s32 [%0], %1;" :: "l"(p), "r"(v) : "memory");
}

// out = base^e, e in [0,3]
__device__ __forceinline__ void pow_e3(const u64* base, int e, u64* out) {
    u64 p0 = pack2(1.0f, 1.0f), p1 = p0;
    u64 b0 = base[0], b1 = base[1];
    if (e & 1) { p0 = mul2_(p0, b0); p1 = mul2_(p1, b1); }
    b0 = mul2_(b0, b0); b1 = mul2_(b1, b1);
    if (e & 2) { p0 = mul2_(p0, b0); p1 = mul2_(p1, b1); }
    out[0] = p0; out[1] = p1;
}

// out = base^e, e in [0,31]
__device__ __forceinline__ void pow_e31(const u64* base, int e, u64* out) {
    u64 p0 = pack2(1.0f, 1.0f), p1 = p0;
    u64 b0 = base[0], b1 = base[1];
    if (e & 1)  { p0 = mul2_(p0, b0); p1 = mul2_(p1, b1); }
    b0 = mul2_(b0, b0); b1 = mul2_(b1, b1);
    if (e & 2)  { p0 = mul2_(p0, b0); p1 = mul2_(p1, b1); }
    b0 = mul2_(b0, b0); b1 = mul2_(b1, b1);
    if (e & 4)  { p0 = mul2_(p0, b0); p1 = mul2_(p1, b1); }
    b0 = mul2_(b0, b0); b1 = mul2_(b1, b1);
    if (e & 8)  { p0 = mul2_(p0, b0); p1 = mul2_(p1, b1); }
    b0 = mul2_(b0, b0); b1 = mul2_(b1, b1);
    if (e & 16) { p0 = mul2_(p0, b0); p1 = mul2_(p1, b1); }
    out[0] = p0; out[1] = p1;
}

// ------------------------------------------------------------------ fused
// Single kernel, single graph node. Grid 1024 = (col, g): 32 columns x 32
// groups; CTA = 128 threads = 4 warps; warp w = chunk g*4+w (16 timesteps).
// occ 8 -> 1024 CTAs in one wave with 7/6 SM balance (was 4/3 at grid 512).
// Coefficients per CTA in smem under the u-load burst. Warp 3 publishes the
// group aggregate; warp 0 receives once (parallel polls + predicated Horner),
// broadcasts via smem. Flags are per-reader slots, reader-reset (no memset).
__global__ __launch_bounds__(128, 8)
void s4_fused(const float* __restrict__ u,
              const float* __restrict__ Dp,
              float* __restrict__ y,
              const float* __restrict__ B_re,
              const float* __restrict__ C_re,
              const float* __restrict__ log_dt)
{
    __shared__ u64   sE[NWARP][MP][32];
    __shared__ u64   sS[MP][32];          // received carry (broadcast)
    __shared__ float sL[NST][M];          // Lagrange basis at true modes
    __shared__ float sAn[NST];            // A_n values
    __shared__ float sDelta[32];          // delta per local h
    __shared__ float sPart[4][32][M];     // c~ partial sums (16 modes each)
    __shared__ float sA[32][M], sC[32][M], sQ[32][M], sQI[32][M];

    const int tid  = threadIdx.x;
    const int col  = blockIdx.x & (NCOL - 1);   // (b, hw)
    const int g    = blockIdx.x >> 5;           // group 0..31; low g = low bid
    const int w    = tid >> 5;                  // 0..3
    const int lane = tid & 31;
    const int b    = col >> 4;
    const int hw   = col & 15;
    const int h    = hw * 32 + lane;

    const int chunk = g * NWARP + w;
    const size_t base = ((size_t)b * SEQLEN + (size_t)chunk * TCH) * H + h;
    const float* ub = u + base;

    // ---- phase A: issue ALL u loads first ----
    float uu[TCH];
#pragma unroll
    for (int t = 0; t < TCH; ++t) uu[t] = ub[(size_t)t * H];

    // ---- phase B: coefficients, hidden under the load burst ----
    if (tid < NST) {
        const float An = rsqrtf(1.0f + (float)(tid + 1) * (1.0f / 64.0f));
        sAn[tid] = An;
#pragma unroll
        for (int m = 0; m < M; ++m) {
            float num = 1.0f, den = 1.0f;
#pragma unroll
            for (int i = 0; i < M; ++i) {
                if (i == m) continue;
                num *= (An - f_node[i]);
                den *= (f_node[m] - f_node[i]);
            }
            sL[tid][m] = num / den;
        }
    }
    if (tid < 32) sDelta[tid] = expf(log_dt[hw * 32 + tid]);
    __syncthreads();

    {
        const int k  = w;          // quartet 0..3: 16 true modes each
        const int hl = lane;
        const float delta = sDelta[hl];
        float cm[M] = {0.0f, 0.0f, 0.0f, 0.0f};
#pragma unroll
        for (int i = 0; i < 16; ++i) {
            const int n = k * 16 + i;
            const float x = delta * sAn[n];                       // <= 1e-3
            const float em = x * fmaf(x, fmaf(x, (1.0f / 6.0f), 0.5f), 1.0f); // expm1
            const float cn = em * B_re[n] * delta * C_re[n];
#pragma unroll
            for (int m = 0; m < M; ++m)
                cm[m] = fmaf(cn, sL[n][m], cm[m]);
        }
#pragma unroll
        for (int m = 0; m < M; ++m) sPart[k][hl][m] = cm[m];

        {   // (hl, m=k): a, q=a^16, qi=1/a^64
            const float x = delta * f_node[k];                    // <= 1e-3
            const float am = 1.0f + x * fmaf(x, fmaf(x, (1.0f / 6.0f), 0.5f), 1.0f);
            float qm = am;
#pragma unroll
            for (int s = 0; s < 4; ++s) qm *= qm;                 // a^16
            float q64 = qm * qm;                                  // a^32
            q64 *= q64;                                           // a^64
            sA[hl][k]  = am;
            sQ[hl][k]  = qm;
            sQI[hl][k] = 1.0f / q64;
        }
    }
    __syncthreads();
    if (tid < 32 * M) {   // reduce c~ over the 4 quartets
        const int hl = tid & 31, m = tid >> 5;
        float s = 0.0f;
#pragma unroll
        for (int k = 0; k < 4; ++k) s += sPart[k][hl][m];
        sC[hl][m] = s;
    }
    __syncthreads();

    u64 a[MP], q[MP];
#pragma unroll
    for (int j = 0; j < MP; ++j) {
        a[j] = pack2(sA[lane][2 * j], sA[lane][2 * j + 1]);
        q[j] = pack2(sQ[lane][2 * j], sQ[lane][2 * j + 1]);
    }

    // ---- local zero-seed scan -> E ----
    u64 z[MP] = {0ull, 0ull};
#pragma unroll
    for (int t = 0; t < TCH; ++t) {
        const u64 ubb = pack2(uu[t], uu[t]);
        z[0] = fma2_(a[0], z[0], ubb);
        z[1] = fma2_(a[1], z[1], ubb);
    }
#pragma unroll
    for (int j = 0; j < MP; ++j) sE[w][j][lane] = z[j];
    __syncthreads();   // sync1: E ready

    // all warps: P_w = sum_{i<w} q^{w-1-i} E_i
    u64 P[MP] = {0ull, 0ull};
    for (int i = 0; i < w; ++i) {
#pragma unroll
        for (int j = 0; j < MP; ++j)
            P[j] = fma2_(q[j], P[j], sE[i][j][lane]);
    }

    // warp 3: publish R_g = q*P_3 + E_3, then fan out per-reader flags
    if (w == NWARP - 1 && g < NGRP - 1) {
        u64* op = g_R + ((size_t)(col * NGRP + g) * MP) * 32 + lane;
#pragma unroll
        for (int j = 0; j < MP; ++j)
            op[(size_t)j * 32] = fma2_(q[j], P[j], z[j]);
        __threadfence();   // order R stores (all lanes) before flag stores
        __syncwarp();
        if (lane > g)      // lane r = reader group id
            st_rel(&g_flag2[(col * NGRP + lane) * NGRP + g], 1);
    }

    // warp 0: receive ONCE; S = sum_{g2<g} qG^{g-1-g2} R_{g2},  qG = q^4
    if (w == 0) {
        u64 S0[MP] = {0ull, 0ull};
        if (g > 0) {
            int* fp = &g_flag2[(col * NGRP + g) * NGRP + lane];
            if (lane < g) {
                while (ld_acq(fp) == 0) { __nanosleep(20); }
                *fp = 0;   // single-reader reset -> clean state for next replay
            }
            __syncwarp();

            u64 qG[MP];
#pragma unroll
            for (int j = 0; j < MP; ++j) {
                const u64 q2v = mul2_(q[j], q[j]);
                qG[j] = mul2_(q2v, q2v);
            }
            // T = sum_{g2=0}^{30} qG^{30-g2} V_{g2} = qG^{31-g} * S (V=R if g2<g)
            u64 T[MP] = {0ull, 0ull};
#pragma unroll
            for (int g2 = 0; g2 < NGRP - 1; ++g2) {
                u64 v0 = 0ull, v1 = 0ull;
                if (g2 < g) {
                    const u64* rp = g_R + ((size_t)(col * NGRP + g2) * MP) * 32 + lane;
                    v0 = rp[0 * 32];
                    v1 = rp[1 * 32];
                }
                T[0] = fma2_(qG[0], T[0], v0);
                T[1] = fma2_(qG[1], T[1], v1);
            }
            // S = T * qGi^{31-g}
            u64 qGi[MP];
#pragma unroll
            for (int j = 0; j < MP; ++j)
                qGi[j] = pack2(sQI[lane][2 * j], sQI[lane][2 * j + 1]);
            u64 pw[MP];
            pow_e31(qGi, (NGRP - 1) - g, pw);
#pragma unroll
            for (int j = 0; j < MP; ++j) S0[j] = mul2_(T[j], pw[j]);
        }
#pragma unroll
        for (int j = 0; j < MP; ++j) sS[j][lane] = S0[j];
    }

    u64 qp[MP];
    pow_e3(q, w, qp);

    __syncthreads();   // sync2: S ready

    // seed = q^w * S + P_w, then output scan (writes y exactly once)
    u64 zz[MP];
#pragma unroll
    for (int j = 0; j < MP; ++j) zz[j] = fma2_(qp[j], sS[j][lane], P[j]);

    u64 c[MP];
#pragma unroll
    for (int j = 0; j < MP; ++j)
        c[j] = pack2(sC[lane][2 * j], sC[lane][2 * j + 1]);
    const float Dh = Dp[h];

    float* yb = y + base;
#pragma unroll
    for (int t = 0; t < TCH; ++t) {
        const u64 ubb = pack2(uu[t], uu[t]);
        zz[0] = fma2_(a[0], zz[0], ubb);
        zz[1] = fma2_(a[1], zz[1], ubb);
        u64 ac0 = fma2_(c[0], zz[0], 0ull);
        ac0 = fma2_(c[1], zz[1], ac0);
        float x0, x1; unpack2(ac0, x0, x1);
        yb[(size_t)t * H] = fmaf(Dh, uu[t], x0 + x1);
    }
}

extern "C" void kernel_launch(void* const* d_in, const int* in_sizes, int n_in,
                              void* d_out, int out_size)
{
    const float* u      = (const float*)d_in[0];
    const float* B_re   = (const float*)d_in[1];
    const float* C_re   = (const float*)d_in[2];
    const float* log_dt = (const float*)d_in[3];
    const float* Dp     = (const float*)d_in[4];
    float* y = (float*)d_out;

    // single node: flags are reader-reset, so no memset is needed
    s4_fused<<<NCOL * NGRP, NWARP * 32>>>(u, Dp, y, B_re, C_re, log_dt);
}